// round 7
// baseline (speedup 1.0000x reference)
#include <cuda_runtime.h>

// LengthRegulator: out[b, t, :] = x[b, j, :] where token j owns frame t
// (cum[j-1] <= t < cum[j]); zero for t >= cum[L-1]. Second output: durations
// echoed back as float. Shapes: N=16, L=512, D=384, T=3584.
//
// Token-major formulation: each 96-lane group reads its token's row ONCE and
// stores it dur times; zero tail handled by dedicated streaming-store blocks.

#define NB 16
#define LL 512
#define DD 384
#define V4 (DD / 4)                 // 96 float4 per frame
#define GROUPS 4                    // token groups per block (96 lanes each)
#define THREADS (V4 * GROUPS)       // 384
#define DATA_BLKS (LL / GROUPS)     // 128 blocks cover 512 tokens
#define ZTILE 32                    // frames per zero-fill block

// Scratch (allocation-free rule: __device__ globals).
__device__ int g_cum[NB * LL];      // inclusive cumsum of durations

// ---------------------------------------------------------------------------
// Kernel 1: prep. 16 blocks x 512 threads: block scan + echo durations.
// ---------------------------------------------------------------------------
__global__ void lr_prep_kernel(const int* __restrict__ dur,
                               float* __restrict__ echo_dst) {
    __shared__ int warp_sums[16];
    const int b = blockIdx.x;
    const int j = threadIdx.x;
    const int lane = j & 31;
    const int w = j >> 5;

    const int d = dur[b * LL + j];

    int inc = d;
#pragma unroll
    for (int off = 1; off < 32; off <<= 1) {
        int v = __shfl_up_sync(0xffffffffu, inc, off);
        if (lane >= off) inc += v;
    }
    if (lane == 31) warp_sums[w] = inc;
    __syncthreads();

    if (w == 0) {
        int s = warp_sums[lane & 15];
#pragma unroll
        for (int off = 1; off < 16; off <<= 1) {
            int v = __shfl_up_sync(0xffffffffu, s, off);
            if ((lane & 15) >= off) s += v;
        }
        if (lane < 16) warp_sums[lane] = s;
    }
    __syncthreads();

    const int c = inc + (w > 0 ? warp_sums[w - 1] : 0);
    g_cum[b * LL + j] = c;

    if (echo_dst) echo_dst[b * LL + j] = (float)d;
}

// ---------------------------------------------------------------------------
// Kernel 2: token-major write + zero tail.
// grid = (DATA_BLKS + T/ZTILE, N), block = 384 (4 groups x 96 lanes).
//  bx <  DATA_BLKS : group g replicates token j = bx*4+g: one float4 row
//                    load, dur coalesced streaming stores (dur uniform per
//                    warp; 96 lanes = 3 whole warps).
//  bx >= DATA_BLKS : zero-fill frames [bx'*32, bx'*32+32) where t >= total.
// Data and zero regions are disjoint by construction.
// ---------------------------------------------------------------------------
__global__ void __launch_bounds__(THREADS)
lr_write_kernel(const float* __restrict__ x,
                const int* __restrict__ dur,
                float* __restrict__ out, int T) {
    const int b = blockIdx.y;
    const int tid = threadIdx.x;
    const int g = tid / V4;          // 0..3
    const int v = tid % V4;          // 0..95
    const int bx = blockIdx.x;

    if (bx < DATA_BLKS) {
        const int j = bx * GROUPS + g;
        const int c = __ldg(&g_cum[b * LL + j]);
        const int d = __ldg(&dur[b * LL + j]);
        if (d == 0) return;
        const int start = c - d;

        const float4 val = __ldg(reinterpret_cast<const float4*>(
                                     x + ((size_t)b * LL + j) * DD) + v);

        float4* ob = reinterpret_cast<float4*>(
                         out + ((size_t)b * T + start) * DD);
#pragma unroll 7
        for (int k = 0; k < d; ++k)
            __stcs(ob + (size_t)k * V4 + v, val);
    } else {
        const int z = bx - DATA_BLKS;
        const int total = __ldg(&g_cum[b * LL + (LL - 1)]);
        const int t0 = z * ZTILE;
        if (t0 + ZTILE <= total) return;     // fully inside data region

        const float4 zero = make_float4(0.f, 0.f, 0.f, 0.f);
        float4* ob = reinterpret_cast<float4*>(out + (size_t)b * T * DD);
#pragma unroll
        for (int k = 0; k < ZTILE / GROUPS; ++k) {
            const int t = t0 + g + k * GROUPS;
            if (t >= total)
                __stcs(ob + (size_t)t * V4 + v, zero);
        }
    }
}

extern "C" void kernel_launch(void* const* d_in, const int* in_sizes, int n_in,
                              void* d_out, int out_size) {
    const float* x = (const float*)d_in[0];
    const int* dur = (const int*)d_in[1];

    const int NL = NB * LL;                          // 8192
    const long long per_frame = (long long)NB * DD;  // 6144 elems per time step

    long long main_elems = out_size;
    float* echo_dst = nullptr;
    if (main_elems % per_frame != 0) {
        main_elems -= NL;
        echo_dst = (float*)d_out + main_elems;
    }
    const int T = (int)(main_elems / per_frame);     // 3584

    lr_prep_kernel<<<NB, LL>>>(dur, echo_dst);

    dim3 grid(DATA_BLKS + T / ZTILE, NB);            // (128+112) x 16
    lr_write_kernel<<<grid, THREADS>>>(x, dur, (float*)d_out, T);
}